// round 14
// baseline (speedup 1.0000x reference)
#include <cuda_runtime.h>
#include <cuda_fp16.h>
#include <math.h>
#include <stdint.h>

#define BATCH 4
#define SEQ   4096
#define DIM   1024
#define MROWS (BATCH*SEQ)       // 16384
#define NCH   256
#define CROWS (SEQ / NCH)       // 16

// ---- mma.sync GEMM tiling (single-term fp16, persistent, 2 CTAs/SM) ----
#define BM 128
#define BN 128
#define NB_CH 16                // K chunks per tile (1024 / 64)
#define NTILES 4096             // 8 nb x 128 mb x 4 sel
#define GRIDP 304               // 2 x 152 SMs
#define STAGES 3
#define A_ST (BM * 128)         // 16384 B
#define B_ST (BN * 128)         // 16384 B
#define STAGE_B (A_ST + B_ST)   // 32768
#define SMEM_DYN (STAGES * STAGE_B)   // 98304  (2 CTAs/SM)

// -------- scratch (static device globals; no runtime allocation) -----------
__device__ __half g_xh[(size_t)MROWS * DIM];      // 32MB  hi only
__device__ __half g_we[4][(size_t)DIM * DIM];     // 8MB   hi only
__device__ float  g_q[(size_t)MROWS * DIM];
__device__ float  g_k[(size_t)MROWS * DIM];
__device__ float  g_v[(size_t)MROWS * DIM];
__device__ float  g_r[(size_t)MROWS * DIM];
__device__ float2 g_part[BATCH * NCH * DIM];
__device__ float2 g_Fs[BATCH * DIM];

// ============================================================================
// helpers
// ============================================================================
__device__ __forceinline__ uint32_t smem_u32(const void* p) {
    uint32_t a;
    asm("{ .reg .u64 t; cvta.to.shared.u64 t, %1; cvt.u32.u64 %0, t; }" : "=r"(a) : "l"(p));
    return a;
}

__device__ __forceinline__ void cp16(uint32_t dst, const void* src) {
    asm volatile("cp.async.cg.shared.global [%0], [%1], 16;" :: "r"(dst), "l"(src) : "memory");
}
#define CP_COMMIT() asm volatile("cp.async.commit_group;" ::: "memory")
#define CP_WAIT1()  asm volatile("cp.async.wait_group 1;" ::: "memory")

__device__ __forceinline__ void ldmx4(uint32_t& r0, uint32_t& r1, uint32_t& r2, uint32_t& r3,
                                      uint32_t addr) {
    asm volatile("ldmatrix.sync.aligned.m8n8.x4.shared.b16 {%0,%1,%2,%3}, [%4];"
                 : "=r"(r0), "=r"(r1), "=r"(r2), "=r"(r3) : "r"(addr));
}

__device__ __forceinline__ void mma16816(float* c, uint32_t a0, uint32_t a1, uint32_t a2,
                                         uint32_t a3, uint32_t b0, uint32_t b1) {
    asm volatile(
        "mma.sync.aligned.m16n8k16.row.col.f32.f16.f16.f32 "
        "{%0,%1,%2,%3}, {%4,%5,%6,%7}, {%8,%9}, {%0,%1,%2,%3};"
        : "+f"(c[0]), "+f"(c[1]), "+f"(c[2]), "+f"(c[3])
        : "r"(a0), "r"(a1), "r"(a2), "r"(a3), "r"(b0), "r"(b1));
}

__device__ __forceinline__ float tanh_fast(float x) {
    float ax = fabsf(x);
    float e = __expf(-2.0f * ax);
    float t = __fdividef(1.0f - e, 1.0f + e);
    return copysignf(t, x);
}

// swizzled smem byte offset within a (rows x 128B) tile
__device__ __forceinline__ uint32_t swz(uint32_t row, uint32_t cg) {
    return row * 128u + ((cg ^ (row & 7u)) << 4);
}

// ============================================================================
// Conversion: fp32 -> fp16 (hi only), x4 vectorized
// ============================================================================
__global__ void __launch_bounds__(256) convert_x_kernel(const float* __restrict__ x)
{
    const size_t base = ((size_t)blockIdx.x * 256 + threadIdx.x) * 4;
    const float4 v = *(const float4*)(x + base);
    __half2 h0 = make_half2(__float2half(v.x), __float2half(v.y));
    __half2 h1 = make_half2(__float2half(v.z), __float2half(v.w));
    __half2* p = (__half2*)(g_xh + base);
    p[0] = h0; p[1] = h1;
}

__global__ void __launch_bounds__(256) convert_w_kernel(
    const float* __restrict__ Wq, const float* __restrict__ Wk,
    const float* __restrict__ Wv, const float* __restrict__ Wr)
{
    const int w = blockIdx.y;
    const float* W = (w == 0) ? Wq : (w == 1) ? Wk : (w == 2) ? Wv : Wr;
    const size_t base = ((size_t)blockIdx.x * 256 + threadIdx.x) * 4;
    const float4 v = *(const float4*)(W + base);
    __half2 h0 = make_half2(__float2half(v.x), __float2half(v.y));
    __half2 h1 = make_half2(__float2half(v.z), __float2half(v.w));
    __half2* p = (__half2*)(g_we[w] + base);
    p[0] = h0; p[1] = h1;
}

// ============================================================================
// PERSISTENT fp16 mma.sync GEMM: C = tanh(Ah@Bh^T + bias)
// grid = GRIDP fixed CTAs; each walks tiles bid, bid+GRIDP, ... with ONE
// continuous cp.async pipeline across tile boundaries (no drain/refill).
// Tile id -> (nb = id&7, mb = (id>>3)&127, sel = id>>10).
// ============================================================================
__global__ void __launch_bounds__(256, 2) gemm_mma_kernel(
    const float* __restrict__ bq, const float* __restrict__ bk,
    const float* __restrict__ bv, const float* __restrict__ br)
{
    extern __shared__ char dsm[];
    const uint32_t smem = smem_u32(dsm);

    const int tid = threadIdx.x, wid = tid >> 5, lane = tid & 31;
    const int bid = blockIdx.x;
    const int wm = wid & 1, wn = wid >> 1;       // warp tile 64(m) x 32(n)

    const int my_nt = (NTILES - 1 - bid) / GRIDP + 1;   // tiles for this CTA
    const int nchunks = my_nt * NB_CH;

    const uint32_t crow0 = (uint32_t)(tid >> 3);   // 0..31
    const uint32_t ccg = (uint32_t)(tid & 7);

    // issue chunk gc (global within this CTA's sequence) into 'stage'
    auto issue = [&](int stage, int gc) {
        const int tile = bid + (gc >> 4) * GRIDP;
        const int bc = gc & 15;
        const int nb = tile & 7, mb = (tile >> 3) & 127, sel = tile >> 10;
        const char* a_base = (const char*)g_xh + (size_t)mb * BM * 2048;
        const char* b_base = (const char*)g_we[sel] + (size_t)nb * BN * 2048;
        const uint32_t sA = smem + stage * STAGE_B;
        const uint32_t sB = sA + A_ST;
#pragma unroll
        for (int j = 0; j < 4; j++) {
            const uint32_t r = crow0 + 32u * j;          // 0..127
            cp16(sA + swz(r, ccg), a_base + (size_t)r * 2048 + bc * 128 + ccg * 16);
        }
#pragma unroll
        for (int j = 0; j < 4; j++) {
            const uint32_t r = crow0 + 32u * j;
            cp16(sB + swz(r, ccg), b_base + (size_t)r * 2048 + bc * 128 + ccg * 16);
        }
    };

    issue(0, 0); CP_COMMIT();
    if (nchunks > 1) issue(1, 1);
    CP_COMMIT();

    const uint32_t a_row = (uint32_t)(wm * 64 + (lane & 15));
    const uint32_t a_kg  = (uint32_t)(lane >> 4);
    const uint32_t b_row = (uint32_t)(wn * 32 + (lane & 7) + ((lane >> 4) << 3));
    const uint32_t b_kg  = (uint32_t)((lane >> 3) & 1);

    int gc = 0;
    for (int lt = 0; lt < my_nt; lt++) {
        const int tile = bid + lt * GRIDP;
        const int nb = tile & 7, mb = (tile >> 3) & 127, sel = tile >> 10;
        const float* bias_g = (sel == 0) ? bq : (sel == 1) ? bk : (sel == 2) ? bv : br;
        float* C = (sel == 0) ? g_q : (sel == 1) ? g_k : (sel == 2) ? g_v : g_r;

        float acc[4][4][4];
#pragma unroll
        for (int i = 0; i < 4; i++)
#pragma unroll
            for (int j = 0; j < 4; j++)
#pragma unroll
                for (int q = 0; q < 4; q++) acc[i][j][q] = 0.f;

        for (int bc = 0; bc < NB_CH; bc++, gc++) {
            const int s = gc % STAGES;
            CP_WAIT1();
            __syncthreads();
            // continuous prefetch across tile boundaries
            if (gc + 2 < nchunks) issue((gc + 2) % STAGES, gc + 2);
            CP_COMMIT();

            const uint32_t sA = smem + s * STAGE_B;
            const uint32_t sB = sA + A_ST;

#pragma unroll
            for (int ks = 0; ks < 4; ks++) {
                uint32_t a[4][4];
#pragma unroll
                for (int mf = 0; mf < 4; mf++)
                    ldmx4(a[mf][0], a[mf][1], a[mf][2], a[mf][3],
                          sA + swz(a_row + mf * 16, a_kg + ks * 2));
                uint32_t b[2][4];
#pragma unroll
                for (int nf2 = 0; nf2 < 2; nf2++)
                    ldmx4(b[nf2][0], b[nf2][1], b[nf2][2], b[nf2][3],
                          sB + swz(b_row + nf2 * 16, b_kg + ks * 2));
#pragma unroll
                for (int mf = 0; mf < 4; mf++) {
#pragma unroll
                    for (int nf2 = 0; nf2 < 2; nf2++) {
                        mma16816(acc[mf][nf2 * 2 + 0], a[mf][0], a[mf][1], a[mf][2], a[mf][3],
                                 b[nf2][0], b[nf2][1]);
                        mma16816(acc[mf][nf2 * 2 + 1], a[mf][0], a[mf][1], a[mf][2], a[mf][3],
                                 b[nf2][2], b[nf2][3]);
                    }
                }
            }
        }

        // epilogue (registers only; next tile's loads already in flight)
#pragma unroll
        for (int mf = 0; mf < 4; mf++) {
            const int r0 = mb * BM + wm * 64 + mf * 16 + (lane >> 2);
            const int r1 = r0 + 8;
#pragma unroll
            for (int nf = 0; nf < 4; nf++) {
                const int col = nb * BN + wn * 32 + nf * 8 + (lane & 3) * 2;
                const float2 b2 = *(const float2*)(bias_g + col);
                float2 o0, o1;
                o0.x = tanh_fast(acc[mf][nf][0] + b2.x);
                o0.y = tanh_fast(acc[mf][nf][1] + b2.y);
                o1.x = tanh_fast(acc[mf][nf][2] + b2.x);
                o1.y = tanh_fast(acc[mf][nf][3] + b2.y);
                *(float2*)(C + (size_t)r0 * DIM + col) = o0;
                *(float2*)(C + (size_t)r1 * DIM + col) = o1;
            }
        }
    }
}

// ============================================================================
// Radix-4 Stockham FFT, N=1024, 256 threads, 5 stages total:
//   stage m=1   : fused with data source (register inputs)   -> smem
//   stages m=4,16,64 : fft_mid3 (smem ping-pong, sync before each)
//   stage m=256 : jm=0, all twiddles = 1 -> fused into REGISTERS
// ============================================================================
__device__ __forceinline__ float2 cmulf(float2 a, float2 b) {
    return make_float2(fmaf(a.x, b.x, -a.y * b.y), fmaf(a.x, b.y, a.y * b.x));
}
__device__ __forceinline__ float2 caddf(float2 a, float2 b) {
    return make_float2(a.x + b.x, a.y + b.y);
}
__device__ __forceinline__ float2 csubf(float2 a, float2 b) {
    return make_float2(a.x - b.x, a.y - b.y);
}

__device__ __forceinline__ void fft_stage1_store(
    float2 x0, float2 x1, float2 x2, float2 x3,
    float2* dst, const float2* tw, int t, int inv)
{
    const float2 t0 = caddf(x0, x2);
    const float2 t1 = caddf(x1, x3);
    const float2 t2 = csubf(x0, x2);
    const float2 d  = csubf(x1, x3);
    const float2 t3 = inv ? make_float2(-d.y, d.x) : make_float2(d.y, -d.x);
    float2 w1 = tw[t];
    if (inv) w1.y = -w1.y;
    const float2 w2 = cmulf(w1, w1);
    const float2 w3 = cmulf(w2, w1);
    const float2 y0 = caddf(t0, t1);
    const float2 y1 = cmulf(w1, caddf(t2, t3));
    const float2 y2 = cmulf(w2, csubf(t0, t1));
    const float2 y3 = cmulf(w3, csubf(t2, t3));
    float4* d4 = (float4*)(dst + 4 * t);
    d4[0] = make_float4(y0.x, y0.y, y1.x, y1.y);
    d4[1] = make_float4(y2.x, y2.y, y3.x, y3.y);
}

__device__ __forceinline__ void fft_mid3(
    float2* a, float2* b, const float2* tw, int t, int inv)
{
    int m = 4;
#pragma unroll
    for (int s = 0; s < 3; s++) {
        __syncthreads();
        const int k  = t & (m - 1);
        const int jm = t - k;
        const float2 x0 = a[t];
        const float2 x1 = a[t + 256];
        const float2 x2 = a[t + 512];
        const float2 x3 = a[t + 768];
        const float2 t0 = caddf(x0, x2);
        const float2 t1 = caddf(x1, x3);
        const float2 t2 = csubf(x0, x2);
        const float2 d  = csubf(x1, x3);
        const float2 t3 = inv ? make_float2(-d.y, d.x) : make_float2(d.y, -d.x);
        float2 w1 = tw[jm];
        if (inv) w1.y = -w1.y;
        const float2 w2 = cmulf(w1, w1);
        const float2 w3 = cmulf(w2, w1);
        const int o = 4 * jm + k;
        b[o]         = caddf(t0, t1);
        b[o + m]     = cmulf(w1, caddf(t2, t3));
        b[o + 2 * m] = cmulf(w2, csubf(t0, t1));
        b[o + 3 * m] = cmulf(w3, csubf(t2, t3));
        float2* tmp = a; a = b; b = tmp;
        m <<= 2;
    }
}

__device__ __forceinline__ void fft_last_reg(
    const float2* src, int t, int inv, float2* Z)
{
    __syncthreads();
    const float2 x0 = src[t];
    const float2 x1 = src[t + 256];
    const float2 x2 = src[t + 512];
    const float2 x3 = src[t + 768];
    const float2 t0 = caddf(x0, x2);
    const float2 t1 = caddf(x1, x3);
    const float2 t2 = csubf(x0, x2);
    const float2 d  = csubf(x1, x3);
    const float2 t3 = inv ? make_float2(-d.y, d.x) : make_float2(d.y, -d.x);
    Z[0] = caddf(t0, t1);
    Z[1] = caddf(t2, t3);
    Z[2] = csubf(t0, t1);
    Z[3] = csubf(t2, t3);
}

__device__ __forceinline__ void build_tw256(float2* tw, int t)
{
    float sn, cs;
    sincosf(-2.0f * (float)M_PI * (float)t * (1.0f / 1024.0f), &sn, &cs);
    tw[t] = make_float2(cs, sn);
}

// ============================================================================
// bind + accumulate with deferred Hermitian extraction
// ============================================================================
__global__ void __launch_bounds__(256) bind_accum_kernel()
{
    __shared__ float2 tw[256];
    __shared__ float2 bufA[1024];
    __shared__ float2 bufB[1024];

    const int t = threadIdx.x;
    const int c = blockIdx.x;
    const int b = blockIdx.y;
    build_tw256(tw, t);

    float2 S[4];
#pragma unroll
    for (int h = 0; h < 4; h++) S[h] = make_float2(0.f, 0.f);

    const size_t base = ((size_t)b * SEQ + (size_t)c * CROWS) * DIM;
    for (int r = 0; r < CROWS; r++) {
        const float* kp = g_k + base + (size_t)r * DIM;
        const float* vp = g_v + base + (size_t)r * DIM;
        fft_stage1_store(
            make_float2(kp[t],       vp[t]),
            make_float2(kp[t + 256], vp[t + 256]),
            make_float2(kp[t + 512], vp[t + 512]),
            make_float2(kp[t + 768], vp[t + 768]),
            bufA, tw, t, 0);
        fft_mid3(bufA, bufB, tw, t, 0);          // output in bufB
        float2 Z[4];
        fft_last_reg(bufB, t, 0, Z);
#pragma unroll
        for (int h = 0; h < 4; h++) {            // S += Z^2
            S[h].x += fmaf(Z[h].x, Z[h].x, -Z[h].y * Z[h].y);
            S[h].y += 2.0f * Z[h].x * Z[h].y;
        }
    }

#pragma unroll
    for (int h = 0; h < 4; h++) bufA[t + (h << 8)] = S[h];
    __syncthreads();
    float2* outp = g_part + ((size_t)b * NCH + c) * DIM;
#pragma unroll
    for (int h = 0; h < 4; h++) {
        const int f  = t + (h << 8);
        const int fn = (1024 - f) & 1023;
        const float2 Sn = bufA[fn];
        const float wr = S[h].x - Sn.x;
        const float wi = S[h].y + Sn.y;
        outp[f] = make_float2(0.25f * wi, -0.25f * wr);
    }
}

__global__ void reduce_Fs_kernel()
{
    const int f = blockIdx.x * 256 + threadIdx.x;
    const int b = blockIdx.y;
    float2 s = make_float2(0.f, 0.f);
    const float2* p = g_part + (size_t)b * NCH * DIM + f;
    for (int c = 0; c < NCH; c++) {
        const float2 v = p[(size_t)c * DIM];
        s.x += v.x; s.y += v.y;
    }
    g_Fs[b * DIM + f] = s;
}

// ============================================================================
// output: two rows per block, combined Hermitian inverse FFT
// ============================================================================
__device__ __forceinline__ void compute_H_reg(
    const float2* Zreg, const float2* Zsm, const float2* Fsb, int t, float2* Hreg)
{
#pragma unroll
    for (int h = 0; h < 4; h++) {
        const int f  = t + (h << 8);
        const int fn = (1024 - f) & 1023;
        const float2 z1 = Zreg[h];
        const float2 z2 = Zsm[fn];
        const float2 Fq = make_float2(0.5f * (z1.x + z2.x), 0.5f * (z1.y - z2.y));
        const float dx = z1.x - z2.x, dy = z1.y + z2.y;
        const float2 Fr = make_float2(0.5f * dy, -0.5f * dx);
        const float mag2 = fmaf(Fr.x, Fr.x, Fr.y * Fr.y);
        const float2 G = make_float2(Fq.x - mag2, -Fq.y);
        Hreg[h] = cmulf(G, Fsb[f]);
    }
}

__global__ void __launch_bounds__(256) output_kernel(
    const float* __restrict__ x, float* __restrict__ out)
{
    __shared__ float2 tw[256];
    __shared__ float2 bufA[1024];
    __shared__ float2 bufB[1024];

    const int t = threadIdx.x;
    const int rowA = blockIdx.x * 2;
    const int rowB = rowA + 1;
    const int b = rowA >> 12;
    build_tw256(tw, t);

    const float2* Fsb = g_Fs + (size_t)b * DIM;
    const size_t baseA = (size_t)rowA * DIM;
    const size_t baseB = (size_t)rowB * DIM;

    // ---- row A forward ----
    {
        const float* qp = g_q + baseA;
        const float* rp = g_r + baseA;
        fft_stage1_store(
            make_float2(qp[t],       rp[t]),
            make_float2(qp[t + 256], rp[t + 256]),
            make_float2(qp[t + 512], rp[t + 512]),
            make_float2(qp[t + 768], rp[t + 768]),
            bufA, tw, t, 0);
    }
    fft_mid3(bufA, bufB, tw, t, 0);
    float2 ZA[4];
    fft_last_reg(bufB, t, 0, ZA);
#pragma unroll
    for (int h = 0; h < 4; h++) bufA[t + (h << 8)] = ZA[h];
    __syncthreads();
    float2 HA[4];
    compute_H_reg(ZA, bufA, Fsb, t, HA);

    // ---- row B forward ----
    {
        const float* qp = g_q + baseB;
        const float* rp = g_r + baseB;
        fft_stage1_store(
            make_float2(qp[t],       rp[t]),
            make_float2(qp[t + 256], rp[t + 256]),
            make_float2(qp[t + 512], rp[t + 512]),
            make_float2(qp[t + 768], rp[t + 768]),
            bufB, tw, t, 0);
    }
    fft_mid3(bufB, bufA, tw, t, 0);
    float2 ZB[4];
    fft_last_reg(bufA, t, 0, ZB);
#pragma unroll
    for (int h = 0; h < 4; h++) bufB[t + (h << 8)] = ZB[h];
    __syncthreads();
    float2 HB[4];
    compute_H_reg(ZB, bufB, Fsb, t, HB);

    // ---- combined inverse: ifft(HA + i*HB) ----
    float2 Hc[4];
#pragma unroll
    for (int h = 0; h < 4; h++)
        Hc[h] = make_float2(HA[h].x - HB[h].y, HA[h].y + HB[h].x);
    fft_stage1_store(Hc[0], Hc[1], Hc[2], Hc[3], bufA, tw, t, 1);
    fft_mid3(bufA, bufB, tw, t, 1);
    float2 R[4];
    fft_last_reg(bufB, t, 1, R);

    const float* xA = x + baseA;
    const float* xB = x + baseB;
    float* oA = out + baseA;
    float* oB = out + baseB;
#pragma unroll
    for (int h = 0; h < 4; h++) {
        const int i = t + (h << 8);
        oA[i] = xA[i] + R[h].x * (1.0f / 1024.0f);
        oB[i] = xB[i] + R[h].y * (1.0f / 1024.0f);
    }
}

// ============================================================================
// Launch
// ============================================================================
extern "C" void kernel_launch(void* const* d_in, const int* in_sizes, int n_in,
                              void* d_out, int out_size)
{
    const float* x  = (const float*)d_in[0];
    const float* Wq = (const float*)d_in[1];
    const float* bq = (const float*)d_in[2];
    const float* Wk = (const float*)d_in[3];
    const float* bk = (const float*)d_in[4];
    const float* Wv = (const float*)d_in[5];
    const float* bv = (const float*)d_in[6];
    const float* Wr = (const float*)d_in[7];
    const float* br = (const float*)d_in[8];
    float* out = (float*)d_out;

    static bool attr_set = false;
    if (!attr_set) {
        cudaFuncSetAttribute(gemm_mma_kernel,
                             cudaFuncAttributeMaxDynamicSharedMemorySize, SMEM_DYN);
        attr_set = true;
    }

    convert_x_kernel<<<(MROWS * DIM) / 1024, 256>>>(x);
    convert_w_kernel<<<dim3((DIM * DIM) / 1024, 4), 256>>>(Wq, Wk, Wv, Wr);

    gemm_mma_kernel<<<GRIDP, 256, SMEM_DYN>>>(bq, bk, bv, br);

    bind_accum_kernel<<<dim3(NCH, BATCH), 256>>>();
    reduce_Fs_kernel<<<dim3(DIM / 256, BATCH), 256>>>();
    output_kernel<<<MROWS / 2, 256>>>(x, out);
}

// round 15
// speedup vs baseline: 1.0166x; 1.0166x over previous
#include <cuda_runtime.h>
#include <cuda_fp16.h>
#include <math.h>
#include <stdint.h>

#define BATCH 4
#define SEQ   4096
#define DIM   1024
#define MROWS (BATCH*SEQ)       // 16384
#define NCH   256
#define CROWS (SEQ / NCH)       // 16

// ---- mma.sync GEMM tiling (single-term fp16, 2 CTAs/SM, 512 threads) ----
#define BM 128
#define BN 128
#define NB_CH 16                // K chunks (1024 / 64)
#define STAGES 3
#define A_ST (BM * 128)         // 16384 B
#define B_ST (BN * 128)         // 16384 B
#define STAGE_B (A_ST + B_ST)   // 32768
#define SMEM_DYN (STAGES * STAGE_B)   // 98304  (2 CTAs/SM)

// -------- scratch (static device globals; no runtime allocation) -----------
__device__ __half g_xh[(size_t)MROWS * DIM];      // 32MB  hi only
__device__ __half g_we[4][(size_t)DIM * DIM];     // 8MB   hi only
__device__ float  g_q[(size_t)MROWS * DIM];
__device__ float  g_k[(size_t)MROWS * DIM];
__device__ float  g_v[(size_t)MROWS * DIM];
__device__ float  g_r[(size_t)MROWS * DIM];
__device__ float2 g_part[BATCH * NCH * DIM];
__device__ float2 g_Fs[BATCH * DIM];

// ============================================================================
// helpers
// ============================================================================
__device__ __forceinline__ uint32_t smem_u32(const void* p) {
    uint32_t a;
    asm("{ .reg .u64 t; cvta.to.shared.u64 t, %1; cvt.u32.u64 %0, t; }" : "=r"(a) : "l"(p));
    return a;
}

__device__ __forceinline__ void cp16(uint32_t dst, const void* src) {
    asm volatile("cp.async.cg.shared.global [%0], [%1], 16;" :: "r"(dst), "l"(src) : "memory");
}
#define CP_COMMIT() asm volatile("cp.async.commit_group;" ::: "memory")
#define CP_WAIT1()  asm volatile("cp.async.wait_group 1;" ::: "memory")

__device__ __forceinline__ void ldmx4(uint32_t& r0, uint32_t& r1, uint32_t& r2, uint32_t& r3,
                                      uint32_t addr) {
    asm volatile("ldmatrix.sync.aligned.m8n8.x4.shared.b16 {%0,%1,%2,%3}, [%4];"
                 : "=r"(r0), "=r"(r1), "=r"(r2), "=r"(r3) : "r"(addr));
}

__device__ __forceinline__ void mma16816(float* c, uint32_t a0, uint32_t a1, uint32_t a2,
                                         uint32_t a3, uint32_t b0, uint32_t b1) {
    asm volatile(
        "mma.sync.aligned.m16n8k16.row.col.f32.f16.f16.f32 "
        "{%0,%1,%2,%3}, {%4,%5,%6,%7}, {%8,%9}, {%0,%1,%2,%3};"
        : "+f"(c[0]), "+f"(c[1]), "+f"(c[2]), "+f"(c[3])
        : "r"(a0), "r"(a1), "r"(a2), "r"(a3), "r"(b0), "r"(b1));
}

__device__ __forceinline__ float tanh_fast(float x) {
    float ax = fabsf(x);
    float e = __expf(-2.0f * ax);
    float t = __fdividef(1.0f - e, 1.0f + e);
    return copysignf(t, x);
}

// swizzled smem byte offset within a (rows x 128B) tile
__device__ __forceinline__ uint32_t swz(uint32_t row, uint32_t cg) {
    return row * 128u + ((cg ^ (row & 7u)) << 4);
}

// ============================================================================
// Merged conversion: one launch covers x (blocks 0..16383) and W (16384..20479)
// ============================================================================
__global__ void __launch_bounds__(256) convert_all_kernel(
    const float* __restrict__ x,
    const float* __restrict__ Wq, const float* __restrict__ Wk,
    const float* __restrict__ Wv, const float* __restrict__ Wr)
{
    const int bid = blockIdx.x;
    if (bid < 16384) {
        const size_t base = ((size_t)bid * 256 + threadIdx.x) * 4;
        const float4 v = *(const float4*)(x + base);
        __half2 h0 = make_half2(__float2half(v.x), __float2half(v.y));
        __half2 h1 = make_half2(__float2half(v.z), __float2half(v.w));
        __half2* p = (__half2*)(g_xh + base);
        p[0] = h0; p[1] = h1;
    } else {
        const int wb = bid - 16384;
        const int w = wb >> 10;
        const float* W = (w == 0) ? Wq : (w == 1) ? Wk : (w == 2) ? Wv : Wr;
        const size_t base = ((size_t)(wb & 1023) * 256 + threadIdx.x) * 4;
        const float4 v = *(const float4*)(W + base);
        __half2 h0 = make_half2(__float2half(v.x), __float2half(v.y));
        __half2 h1 = make_half2(__float2half(v.z), __float2half(v.w));
        __half2* p = (__half2*)(g_we[w] + base);
        p[0] = h0; p[1] = h1;
    }
}

// ============================================================================
// fp16 mma.sync GEMM (single term): C = tanh(Ah@Bh^T + bias)
// BM=128 x BN=128, 16 warps (warp 32x32), 2 CTAs/SM, grid.z = weight.
// 8 warps/SMSP hide LDSM->HMMA latency via arbitration (acc only 32 regs).
// ============================================================================
__global__ void __launch_bounds__(512, 2) gemm_mma_kernel(
    const float* __restrict__ bq, const float* __restrict__ bk,
    const float* __restrict__ bv, const float* __restrict__ br)
{
    extern __shared__ char dsm[];
    const uint32_t smem = smem_u32(dsm);

    const int tid = threadIdx.x, wid = tid >> 5, lane = tid & 31;
    const int nb = blockIdx.x, mb = blockIdx.y, sel = blockIdx.z;
    const int wm = wid & 3, wn = wid >> 2;       // warp tile 32(m) x 32(n)
    const float* bias_g = (sel == 0) ? bq : (sel == 1) ? bk : (sel == 2) ? bv : br;
    float* C = (sel == 0) ? g_q : (sel == 1) ? g_k : (sel == 2) ? g_v : g_r;

    const char* a_base = (const char*)g_xh + (size_t)mb * BM * 2048;      // 2048B/row
    const char* b_base = (const char*)g_we[sel] + (size_t)nb * BN * 2048; // 2048B/row

    const uint32_t crow0 = (uint32_t)(tid >> 3);   // 0..63
    const uint32_t ccg = (uint32_t)(tid & 7);

    float acc[2][4][4];
#pragma unroll
    for (int i = 0; i < 2; i++)
#pragma unroll
        for (int j = 0; j < 4; j++)
#pragma unroll
            for (int q = 0; q < 4; q++) acc[i][j][q] = 0.f;

    auto issue = [&](int stage, int bc) {
        const uint32_t sA = smem + stage * STAGE_B;
        const uint32_t sB = sA + A_ST;
#pragma unroll
        for (int j = 0; j < 2; j++) {
            const uint32_t r = crow0 + 64u * j;          // 0..127
            cp16(sA + swz(r, ccg), a_base + (size_t)r * 2048 + bc * 128 + ccg * 16);
        }
#pragma unroll
        for (int j = 0; j < 2; j++) {
            const uint32_t r = crow0 + 64u * j;
            cp16(sB + swz(r, ccg), b_base + (size_t)r * 2048 + bc * 128 + ccg * 16);
        }
    };

    issue(0, 0); CP_COMMIT();
    issue(1, 1); CP_COMMIT();

    const uint32_t a_row = (uint32_t)(wm * 32 + (lane & 15));
    const uint32_t a_kg  = (uint32_t)(lane >> 4);
    const uint32_t b_row = (uint32_t)(wn * 32 + (lane & 7) + ((lane >> 4) << 3));
    const uint32_t b_kg  = (uint32_t)((lane >> 3) & 1);

    for (int bc = 0; bc < NB_CH; bc++) {
        const int s = bc % STAGES;
        CP_WAIT1();
        __syncthreads();
        // early prefetch: the target stage was consumed last iteration
        if (bc + 2 < NB_CH) issue((bc + 2) % STAGES, bc + 2);
        CP_COMMIT();

        const uint32_t sA = smem + s * STAGE_B;
        const uint32_t sB = sA + A_ST;

#pragma unroll
        for (int ks = 0; ks < 4; ks++) {
            uint32_t a[2][4];
#pragma unroll
            for (int mf = 0; mf < 2; mf++)
                ldmx4(a[mf][0], a[mf][1], a[mf][2], a[mf][3],
                      sA + swz(a_row + mf * 16, a_kg + ks * 2));
            uint32_t b[2][4];
#pragma unroll
            for (int nf2 = 0; nf2 < 2; nf2++)
                ldmx4(b[nf2][0], b[nf2][1], b[nf2][2], b[nf2][3],
                      sB + swz(b_row + nf2 * 16, b_kg + ks * 2));
#pragma unroll
            for (int mf = 0; mf < 2; mf++) {
#pragma unroll
                for (int nf2 = 0; nf2 < 2; nf2++) {
                    mma16816(acc[mf][nf2 * 2 + 0], a[mf][0], a[mf][1], a[mf][2], a[mf][3],
                             b[nf2][0], b[nf2][1]);
                    mma16816(acc[mf][nf2 * 2 + 1], a[mf][0], a[mf][1], a[mf][2], a[mf][3],
                             b[nf2][2], b[nf2][3]);
                }
            }
        }
    }

    // epilogue: bias + tanh + fp32 store
#pragma unroll
    for (int mf = 0; mf < 2; mf++) {
        const int r0 = mb * BM + wm * 32 + mf * 16 + (lane >> 2);
        const int r1 = r0 + 8;
#pragma unroll
        for (int nf = 0; nf < 4; nf++) {
            const int col = nb * BN + wn * 32 + nf * 8 + (lane & 3) * 2;
            const float2 b2 = *(const float2*)(bias_g + col);
            float2 o0, o1;
            o0.x = tanh_fast(acc[mf][nf][0] + b2.x);
            o0.y = tanh_fast(acc[mf][nf][1] + b2.y);
            o1.x = tanh_fast(acc[mf][nf][2] + b2.x);
            o1.y = tanh_fast(acc[mf][nf][3] + b2.y);
            *(float2*)(C + (size_t)r0 * DIM + col) = o0;
            *(float2*)(C + (size_t)r1 * DIM + col) = o1;
        }
    }
}

// ============================================================================
// Radix-4 Stockham FFT, N=1024, 256 threads, 5 stages total:
//   stage m=1   : fused with data source (register inputs)   -> smem
//   stages m=4,16,64 : fft_mid3 (smem ping-pong, sync before each)
//   stage m=256 : jm=0, all twiddles = 1 -> fused into REGISTERS
// ============================================================================
__device__ __forceinline__ float2 cmulf(float2 a, float2 b) {
    return make_float2(fmaf(a.x, b.x, -a.y * b.y), fmaf(a.x, b.y, a.y * b.x));
}
__device__ __forceinline__ float2 caddf(float2 a, float2 b) {
    return make_float2(a.x + b.x, a.y + b.y);
}
__device__ __forceinline__ float2 csubf(float2 a, float2 b) {
    return make_float2(a.x - b.x, a.y - b.y);
}

__device__ __forceinline__ void fft_stage1_store(
    float2 x0, float2 x1, float2 x2, float2 x3,
    float2* dst, const float2* tw, int t, int inv)
{
    const float2 t0 = caddf(x0, x2);
    const float2 t1 = caddf(x1, x3);
    const float2 t2 = csubf(x0, x2);
    const float2 d  = csubf(x1, x3);
    const float2 t3 = inv ? make_float2(-d.y, d.x) : make_float2(d.y, -d.x);
    float2 w1 = tw[t];
    if (inv) w1.y = -w1.y;
    const float2 w2 = cmulf(w1, w1);
    const float2 w3 = cmulf(w2, w1);
    const float2 y0 = caddf(t0, t1);
    const float2 y1 = cmulf(w1, caddf(t2, t3));
    const float2 y2 = cmulf(w2, csubf(t0, t1));
    const float2 y3 = cmulf(w3, csubf(t2, t3));
    float4* d4 = (float4*)(dst + 4 * t);
    d4[0] = make_float4(y0.x, y0.y, y1.x, y1.y);
    d4[1] = make_float4(y2.x, y2.y, y3.x, y3.y);
}

__device__ __forceinline__ void fft_mid3(
    float2* a, float2* b, const float2* tw, int t, int inv)
{
    int m = 4;
#pragma unroll
    for (int s = 0; s < 3; s++) {
        __syncthreads();
        const int k  = t & (m - 1);
        const int jm = t - k;
        const float2 x0 = a[t];
        const float2 x1 = a[t + 256];
        const float2 x2 = a[t + 512];
        const float2 x3 = a[t + 768];
        const float2 t0 = caddf(x0, x2);
        const float2 t1 = caddf(x1, x3);
        const float2 t2 = csubf(x0, x2);
        const float2 d  = csubf(x1, x3);
        const float2 t3 = inv ? make_float2(-d.y, d.x) : make_float2(d.y, -d.x);
        float2 w1 = tw[jm];
        if (inv) w1.y = -w1.y;
        const float2 w2 = cmulf(w1, w1);
        const float2 w3 = cmulf(w2, w1);
        const int o = 4 * jm + k;
        b[o]         = caddf(t0, t1);
        b[o + m]     = cmulf(w1, caddf(t2, t3));
        b[o + 2 * m] = cmulf(w2, csubf(t0, t1));
        b[o + 3 * m] = cmulf(w3, csubf(t2, t3));
        float2* tmp = a; a = b; b = tmp;
        m <<= 2;
    }
}

__device__ __forceinline__ void fft_last_reg(
    const float2* src, int t, int inv, float2* Z)
{
    __syncthreads();
    const float2 x0 = src[t];
    const float2 x1 = src[t + 256];
    const float2 x2 = src[t + 512];
    const float2 x3 = src[t + 768];
    const float2 t0 = caddf(x0, x2);
    const float2 t1 = caddf(x1, x3);
    const float2 t2 = csubf(x0, x2);
    const float2 d  = csubf(x1, x3);
    const float2 t3 = inv ? make_float2(-d.y, d.x) : make_float2(d.y, -d.x);
    Z[0] = caddf(t0, t1);
    Z[1] = caddf(t2, t3);
    Z[2] = csubf(t0, t1);
    Z[3] = csubf(t2, t3);
}

__device__ __forceinline__ void build_tw256(float2* tw, int t)
{
    float sn, cs;
    sincosf(-2.0f * (float)M_PI * (float)t * (1.0f / 1024.0f), &sn, &cs);
    tw[t] = make_float2(cs, sn);
}

// ============================================================================
// bind + accumulate with deferred Hermitian extraction:
//   per row: S[f] += Z[f]^2 ; end: acc = (S[f] - conj(S[fn]))/(4i)
// ============================================================================
__global__ void __launch_bounds__(256) bind_accum_kernel()
{
    __shared__ float2 tw[256];
    __shared__ float2 bufA[1024];
    __shared__ float2 bufB[1024];

    const int t = threadIdx.x;
    const int c = blockIdx.x;
    const int b = blockIdx.y;
    build_tw256(tw, t);

    float2 S[4];
#pragma unroll
    for (int h = 0; h < 4; h++) S[h] = make_float2(0.f, 0.f);

    const size_t base = ((size_t)b * SEQ + (size_t)c * CROWS) * DIM;
    for (int r = 0; r < CROWS; r++) {
        const float* kp = g_k + base + (size_t)r * DIM;
        const float* vp = g_v + base + (size_t)r * DIM;
        fft_stage1_store(
            make_float2(kp[t],       vp[t]),
            make_float2(kp[t + 256], vp[t + 256]),
            make_float2(kp[t + 512], vp[t + 512]),
            make_float2(kp[t + 768], vp[t + 768]),
            bufA, tw, t, 0);
        fft_mid3(bufA, bufB, tw, t, 0);          // output in bufB
        float2 Z[4];
        fft_last_reg(bufB, t, 0, Z);
#pragma unroll
        for (int h = 0; h < 4; h++) {            // S += Z^2
            S[h].x += fmaf(Z[h].x, Z[h].x, -Z[h].y * Z[h].y);
            S[h].y += 2.0f * Z[h].x * Z[h].y;
        }
    }

#pragma unroll
    for (int h = 0; h < 4; h++) bufA[t + (h << 8)] = S[h];
    __syncthreads();
    float2* outp = g_part + ((size_t)b * NCH + c) * DIM;
#pragma unroll
    for (int h = 0; h < 4; h++) {
        const int f  = t + (h << 8);
        const int fn = (1024 - f) & 1023;
        const float2 Sn = bufA[fn];
        const float wr = S[h].x - Sn.x;
        const float wi = S[h].y + Sn.y;
        outp[f] = make_float2(0.25f * wi, -0.25f * wr);
    }
}

__global__ void reduce_Fs_kernel()
{
    const int f = blockIdx.x * 256 + threadIdx.x;
    const int b = blockIdx.y;
    float2 s = make_float2(0.f, 0.f);
    const float2* p = g_part + (size_t)b * NCH * DIM + f;
    for (int c = 0; c < NCH; c++) {
        const float2 v = p[(size_t)c * DIM];
        s.x += v.x; s.y += v.y;
    }
    g_Fs[b * DIM + f] = s;
}

// ============================================================================
// output: two rows per block, combined Hermitian inverse FFT
// ============================================================================
__device__ __forceinline__ void compute_H_reg(
    const float2* Zreg, const float2* Zsm, const float2* Fsb, int t, float2* Hreg)
{
#pragma unroll
    for (int h = 0; h < 4; h++) {
        const int f  = t + (h << 8);
        const int fn = (1024 - f) & 1023;
        const float2 z1 = Zreg[h];
        const float2 z2 = Zsm[fn];
        const float2 Fq = make_float2(0.5f * (z1.x + z2.x), 0.5f * (z1.y - z2.y));
        const float dx = z1.x - z2.x, dy = z1.y + z2.y;
        const float2 Fr = make_float2(0.5f * dy, -0.5f * dx);
        const float mag2 = fmaf(Fr.x, Fr.x, Fr.y * Fr.y);
        const float2 G = make_float2(Fq.x - mag2, -Fq.y);
        Hreg[h] = cmulf(G, Fsb[f]);
    }
}

__global__ void __launch_bounds__(256) output_kernel(
    const float* __restrict__ x, float* __restrict__ out)
{
    __shared__ float2 tw[256];
    __shared__ float2 bufA[1024];
    __shared__ float2 bufB[1024];

    const int t = threadIdx.x;
    const int rowA = blockIdx.x * 2;
    const int rowB = rowA + 1;
    const int b = rowA >> 12;
    build_tw256(tw, t);

    const float2* Fsb = g_Fs + (size_t)b * DIM;
    const size_t baseA = (size_t)rowA * DIM;
    const size_t baseB = (size_t)rowB * DIM;

    // ---- row A forward ----
    {
        const float* qp = g_q + baseA;
        const float* rp = g_r + baseA;
        fft_stage1_store(
            make_float2(qp[t],       rp[t]),
            make_float2(qp[t + 256], rp[t + 256]),
            make_float2(qp[t + 512], rp[t + 512]),
            make_float2(qp[t + 768], rp[t + 768]),
            bufA, tw, t, 0);
    }
    fft_mid3(bufA, bufB, tw, t, 0);
    float2 ZA[4];
    fft_last_reg(bufB, t, 0, ZA);
#pragma unroll
    for (int h = 0; h < 4; h++) bufA[t + (h << 8)] = ZA[h];
    __syncthreads();
    float2 HA[4];
    compute_H_reg(ZA, bufA, Fsb, t, HA);

    // ---- row B forward ----
    {
        const float* qp = g_q + baseB;
        const float* rp = g_r + baseB;
        fft_stage1_store(
            make_float2(qp[t],       rp[t]),
            make_float2(qp[t + 256], rp[t + 256]),
            make_float2(qp[t + 512], rp[t + 512]),
            make_float2(qp[t + 768], rp[t + 768]),
            bufB, tw, t, 0);
    }
    fft_mid3(bufB, bufA, tw, t, 0);
    float2 ZB[4];
    fft_last_reg(bufA, t, 0, ZB);
#pragma unroll
    for (int h = 0; h < 4; h++) bufB[t + (h << 8)] = ZB[h];
    __syncthreads();
    float2 HB[4];
    compute_H_reg(ZB, bufB, Fsb, t, HB);

    // ---- combined inverse: ifft(HA + i*HB) ----
    float2 Hc[4];
#pragma unroll
    for (int h = 0; h < 4; h++)
        Hc[h] = make_float2(HA[h].x - HB[h].y, HA[h].y + HB[h].x);
    fft_stage1_store(Hc[0], Hc[1], Hc[2], Hc[3], bufA, tw, t, 1);
    fft_mid3(bufA, bufB, tw, t, 1);
    float2 R[4];
    fft_last_reg(bufB, t, 1, R);

    const float* xA = x + baseA;
    const float* xB = x + baseB;
    float* oA = out + baseA;
    float* oB = out + baseB;
#pragma unroll
    for (int h = 0; h < 4; h++) {
        const int i = t + (h << 8);
        oA[i] = xA[i] + R[h].x * (1.0f / 1024.0f);
        oB[i] = xB[i] + R[h].y * (1.0f / 1024.0f);
    }
}

// ============================================================================
// Launch
// ============================================================================
extern "C" void kernel_launch(void* const* d_in, const int* in_sizes, int n_in,
                              void* d_out, int out_size)
{
    const float* x  = (const float*)d_in[0];
    const float* Wq = (const float*)d_in[1];
    const float* bq = (const float*)d_in[2];
    const float* Wk = (const float*)d_in[3];
    const float* bk = (const float*)d_in[4];
    const float* Wv = (const float*)d_in[5];
    const float* bv = (const float*)d_in[6];
    const float* Wr = (const float*)d_in[7];
    const float* br = (const float*)d_in[8];
    float* out = (float*)d_out;

    static bool attr_set = false;
    if (!attr_set) {
        cudaFuncSetAttribute(gemm_mma_kernel,
                             cudaFuncAttributeMaxDynamicSharedMemorySize, SMEM_DYN);
        attr_set = true;
    }

    convert_all_kernel<<<16384 + 4096, 256>>>(x, Wq, Wk, Wv, Wr);

    gemm_mma_kernel<<<dim3(DIM / BN, MROWS / BM, 4), 512, SMEM_DYN>>>(bq, bk, bv, br);

    bind_accum_kernel<<<dim3(NCH, BATCH), 256>>>();
    reduce_Fs_kernel<<<dim3(DIM / 256, BATCH), 256>>>();
    output_kernel<<<MROWS / 2, 256>>>(x, out);
}

// round 16
// speedup vs baseline: 1.0640x; 1.0467x over previous
#include <cuda_runtime.h>
#include <cuda_fp16.h>
#include <math.h>
#include <stdint.h>

#define BATCH 4
#define SEQ   4096
#define DIM   1024
#define MROWS (BATCH*SEQ)       // 16384
#define NCH   256
#define CROWS (SEQ / NCH)       // 16

// ---- mma.sync GEMM tiling (single-term fp16, 2 CTAs/SM) ----
#define BM 128
#define BN 128
#define NB_CH 16                // K chunks (1024 / 64)
#define STAGES 3
#define A_ST (BM * 128)         // 16384 B
#define B_ST (BN * 128)         // 16384 B
#define STAGE_B (A_ST + B_ST)   // 32768
#define SMEM_DYN (STAGES * STAGE_B)   // 98304  (2 CTAs/SM)

// -------- scratch (static device globals; no runtime allocation) -----------
__device__ __half g_xh[(size_t)MROWS * DIM];      // 32MB  hi only
__device__ __half g_we[4][(size_t)DIM * DIM];     // 8MB   hi only
__device__ float  g_q[(size_t)MROWS * DIM];
__device__ float  g_k[(size_t)MROWS * DIM];
__device__ float  g_v[(size_t)MROWS * DIM];
__device__ float  g_r[(size_t)MROWS * DIM];
__device__ float2 g_part[BATCH * NCH * DIM];
__device__ float2 g_Fs[BATCH * DIM];

// ============================================================================
// helpers
// ============================================================================
__device__ __forceinline__ uint32_t smem_u32(const void* p) {
    uint32_t a;
    asm("{ .reg .u64 t; cvta.to.shared.u64 t, %1; cvt.u32.u64 %0, t; }" : "=r"(a) : "l"(p));
    return a;
}

__device__ __forceinline__ void cp16(uint32_t dst, const void* src) {
    asm volatile("cp.async.cg.shared.global [%0], [%1], 16;" :: "r"(dst), "l"(src) : "memory");
}
#define CP_COMMIT() asm volatile("cp.async.commit_group;" ::: "memory")
#define CP_WAIT1()  asm volatile("cp.async.wait_group 1;" ::: "memory")

__device__ __forceinline__ void ldmx4(uint32_t& r0, uint32_t& r1, uint32_t& r2, uint32_t& r3,
                                      uint32_t addr) {
    asm volatile("ldmatrix.sync.aligned.m8n8.x4.shared.b16 {%0,%1,%2,%3}, [%4];"
                 : "=r"(r0), "=r"(r1), "=r"(r2), "=r"(r3) : "r"(addr));
}

__device__ __forceinline__ void mma16816(float* c, uint32_t a0, uint32_t a1, uint32_t a2,
                                         uint32_t a3, uint32_t b0, uint32_t b1) {
    asm volatile(
        "mma.sync.aligned.m16n8k16.row.col.f32.f16.f16.f32 "
        "{%0,%1,%2,%3}, {%4,%5,%6,%7}, {%8,%9}, {%0,%1,%2,%3};"
        : "+f"(c[0]), "+f"(c[1]), "+f"(c[2]), "+f"(c[3])
        : "r"(a0), "r"(a1), "r"(a2), "r"(a3), "r"(b0), "r"(b1));
}

__device__ __forceinline__ float tanh_fast(float x) {
    float ax = fabsf(x);
    float e = __expf(-2.0f * ax);
    float t = __fdividef(1.0f - e, 1.0f + e);
    return copysignf(t, x);
}

// swizzled smem byte offset within a (rows x 128B) tile
__device__ __forceinline__ uint32_t swz(uint32_t row, uint32_t cg) {
    return row * 128u + ((cg ^ (row & 7u)) << 4);
}

// ============================================================================
// Merged conversion: one launch covers x (blocks 0..16383) and W (16384..20479)
// ============================================================================
__global__ void __launch_bounds__(256) convert_all_kernel(
    const float* __restrict__ x,
    const float* __restrict__ Wq, const float* __restrict__ Wk,
    const float* __restrict__ Wv, const float* __restrict__ Wr)
{
    const int bid = blockIdx.x;
    if (bid < 16384) {
        const size_t base = ((size_t)bid * 256 + threadIdx.x) * 4;
        const float4 v = *(const float4*)(x + base);
        __half2 h0 = make_half2(__float2half(v.x), __float2half(v.y));
        __half2 h1 = make_half2(__float2half(v.z), __float2half(v.w));
        __half2* p = (__half2*)(g_xh + base);
        p[0] = h0; p[1] = h1;
    } else {
        const int wb = bid - 16384;
        const int w = wb >> 10;
        const float* W = (w == 0) ? Wq : (w == 1) ? Wk : (w == 2) ? Wv : Wr;
        const size_t base = ((size_t)(wb & 1023) * 256 + threadIdx.x) * 4;
        const float4 v = *(const float4*)(W + base);
        __half2 h0 = make_half2(__float2half(v.x), __float2half(v.y));
        __half2 h1 = make_half2(__float2half(v.z), __float2half(v.w));
        __half2* p = (__half2*)(g_we[w] + base);
        p[0] = h0; p[1] = h1;
    }
}

// ============================================================================
// fp16 mma.sync GEMM (single term): C = tanh(Ah@Bh^T + bias)
// BM=128 x BN=128, 8 warps (warp 64x32), 2 CTAs/SM. grid.z selects weight.
// (round-13 configuration — best measured)
// ============================================================================
__global__ void __launch_bounds__(256, 2) gemm_mma_kernel(
    const float* __restrict__ bq, const float* __restrict__ bk,
    const float* __restrict__ bv, const float* __restrict__ br)
{
    extern __shared__ char dsm[];
    const uint32_t smem = smem_u32(dsm);

    const int tid = threadIdx.x, wid = tid >> 5, lane = tid & 31;
    const int nb = blockIdx.x, mb = blockIdx.y, sel = blockIdx.z;
    const int wm = wid & 1, wn = wid >> 1;       // warp tile 64(m) x 32(n)
    const float* bias_g = (sel == 0) ? bq : (sel == 1) ? bk : (sel == 2) ? bv : br;
    float* C = (sel == 0) ? g_q : (sel == 1) ? g_k : (sel == 2) ? g_v : g_r;

    const char* a_base = (const char*)g_xh + (size_t)mb * BM * 2048;      // 2048B/row
    const char* b_base = (const char*)g_we[sel] + (size_t)nb * BN * 2048; // 2048B/row

    const uint32_t crow0 = (uint32_t)(tid >> 3);   // 0..31
    const uint32_t ccg = (uint32_t)(tid & 7);

    float acc[4][4][4];
#pragma unroll
    for (int i = 0; i < 4; i++)
#pragma unroll
        for (int j = 0; j < 4; j++)
#pragma unroll
            for (int q = 0; q < 4; q++) acc[i][j][q] = 0.f;

    auto issue = [&](int stage, int bc) {
        const uint32_t sA = smem + stage * STAGE_B;
        const uint32_t sB = sA + A_ST;
#pragma unroll
        for (int j = 0; j < 4; j++) {
            const uint32_t r = crow0 + 32u * j;          // 0..127
            cp16(sA + swz(r, ccg), a_base + (size_t)r * 2048 + bc * 128 + ccg * 16);
        }
#pragma unroll
        for (int j = 0; j < 4; j++) {
            const uint32_t r = crow0 + 32u * j;
            cp16(sB + swz(r, ccg), b_base + (size_t)r * 2048 + bc * 128 + ccg * 16);
        }
    };

    issue(0, 0); CP_COMMIT();
    issue(1, 1); CP_COMMIT();

    const uint32_t a_row = (uint32_t)(wm * 64 + (lane & 15));
    const uint32_t a_kg  = (uint32_t)(lane >> 4);
    const uint32_t b_row = (uint32_t)(wn * 32 + (lane & 7) + ((lane >> 4) << 3));
    const uint32_t b_kg  = (uint32_t)((lane >> 3) & 1);

    for (int bc = 0; bc < NB_CH; bc++) {
        const int s = bc % STAGES;
        CP_WAIT1();
        __syncthreads();
        if (bc + 2 < NB_CH) issue((bc + 2) % STAGES, bc + 2);
        CP_COMMIT();

        const uint32_t sA = smem + s * STAGE_B;
        const uint32_t sB = sA + A_ST;

#pragma unroll
        for (int ks = 0; ks < 4; ks++) {
            uint32_t a[4][4];
#pragma unroll
            for (int mf = 0; mf < 4; mf++)
                ldmx4(a[mf][0], a[mf][1], a[mf][2], a[mf][3],
                      sA + swz(a_row + mf * 16, a_kg + ks * 2));
            uint32_t b[2][4];
#pragma unroll
            for (int nf2 = 0; nf2 < 2; nf2++)
                ldmx4(b[nf2][0], b[nf2][1], b[nf2][2], b[nf2][3],
                      sB + swz(b_row + nf2 * 16, b_kg + ks * 2));
#pragma unroll
            for (int mf = 0; mf < 4; mf++) {
#pragma unroll
                for (int nf2 = 0; nf2 < 2; nf2++) {
                    mma16816(acc[mf][nf2 * 2 + 0], a[mf][0], a[mf][1], a[mf][2], a[mf][3],
                             b[nf2][0], b[nf2][1]);
                    mma16816(acc[mf][nf2 * 2 + 1], a[mf][0], a[mf][1], a[mf][2], a[mf][3],
                             b[nf2][2], b[nf2][3]);
                }
            }
        }
    }

    // epilogue: bias + tanh + fp32 store
#pragma unroll
    for (int mf = 0; mf < 4; mf++) {
        const int r0 = mb * BM + wm * 64 + mf * 16 + (lane >> 2);
        const int r1 = r0 + 8;
#pragma unroll
        for (int nf = 0; nf < 4; nf++) {
            const int col = nb * BN + wn * 32 + nf * 8 + (lane & 3) * 2;
            const float2 b2 = *(const float2*)(bias_g + col);
            float2 o0, o1;
            o0.x = tanh_fast(acc[mf][nf][0] + b2.x);
            o0.y = tanh_fast(acc[mf][nf][1] + b2.y);
            o1.x = tanh_fast(acc[mf][nf][2] + b2.x);
            o1.y = tanh_fast(acc[mf][nf][3] + b2.y);
            *(float2*)(C + (size_t)r0 * DIM + col) = o0;
            *(float2*)(C + (size_t)r1 * DIM + col) = o1;
        }
    }
}

// ============================================================================
// Radix-4 Stockham FFT, N=1024, 256 threads, 5 stages total:
//   stage m=1   : fused with data source (register inputs)   -> smem
//   stages m=4,16,64 : fft_mid3 (smem ping-pong, sync before each)
//   stage m=256 : jm=0, all twiddles = 1 -> fused into REGISTERS
// ============================================================================
__device__ __forceinline__ float2 cmulf(float2 a, float2 b) {
    return make_float2(fmaf(a.x, b.x, -a.y * b.y), fmaf(a.x, b.y, a.y * b.x));
}
__device__ __forceinline__ float2 caddf(float2 a, float2 b) {
    return make_float2(a.x + b.x, a.y + b.y);
}
__device__ __forceinline__ float2 csubf(float2 a, float2 b) {
    return make_float2(a.x - b.x, a.y - b.y);
}

__device__ __forceinline__ void fft_stage1_store(
    float2 x0, float2 x1, float2 x2, float2 x3,
    float2* dst, const float2* tw, int t, int inv)
{
    const float2 t0 = caddf(x0, x2);
    const float2 t1 = caddf(x1, x3);
    const float2 t2 = csubf(x0, x2);
    const float2 d  = csubf(x1, x3);
    const float2 t3 = inv ? make_float2(-d.y, d.x) : make_float2(d.y, -d.x);
    float2 w1 = tw[t];
    if (inv) w1.y = -w1.y;
    const float2 w2 = cmulf(w1, w1);
    const float2 w3 = cmulf(w2, w1);
    const float2 y0 = caddf(t0, t1);
    const float2 y1 = cmulf(w1, caddf(t2, t3));
    const float2 y2 = cmulf(w2, csubf(t0, t1));
    const float2 y3 = cmulf(w3, csubf(t2, t3));
    float4* d4 = (float4*)(dst + 4 * t);
    d4[0] = make_float4(y0.x, y0.y, y1.x, y1.y);
    d4[1] = make_float4(y2.x, y2.y, y3.x, y3.y);
}

__device__ __forceinline__ void fft_mid3(
    float2* a, float2* b, const float2* tw, int t, int inv)
{
    int m = 4;
#pragma unroll
    for (int s = 0; s < 3; s++) {
        __syncthreads();
        const int k  = t & (m - 1);
        const int jm = t - k;
        const float2 x0 = a[t];
        const float2 x1 = a[t + 256];
        const float2 x2 = a[t + 512];
        const float2 x3 = a[t + 768];
        const float2 t0 = caddf(x0, x2);
        const float2 t1 = caddf(x1, x3);
        const float2 t2 = csubf(x0, x2);
        const float2 d  = csubf(x1, x3);
        const float2 t3 = inv ? make_float2(-d.y, d.x) : make_float2(d.y, -d.x);
        float2 w1 = tw[jm];
        if (inv) w1.y = -w1.y;
        const float2 w2 = cmulf(w1, w1);
        const float2 w3 = cmulf(w2, w1);
        const int o = 4 * jm + k;
        b[o]         = caddf(t0, t1);
        b[o + m]     = cmulf(w1, caddf(t2, t3));
        b[o + 2 * m] = cmulf(w2, csubf(t0, t1));
        b[o + 3 * m] = cmulf(w3, csubf(t2, t3));
        float2* tmp = a; a = b; b = tmp;
        m <<= 2;
    }
}

__device__ __forceinline__ void fft_last_reg(
    const float2* src, int t, int inv, float2* Z)
{
    __syncthreads();
    const float2 x0 = src[t];
    const float2 x1 = src[t + 256];
    const float2 x2 = src[t + 512];
    const float2 x3 = src[t + 768];
    const float2 t0 = caddf(x0, x2);
    const float2 t1 = caddf(x1, x3);
    const float2 t2 = csubf(x0, x2);
    const float2 d  = csubf(x1, x3);
    const float2 t3 = inv ? make_float2(-d.y, d.x) : make_float2(d.y, -d.x);
    Z[0] = caddf(t0, t1);
    Z[1] = caddf(t2, t3);
    Z[2] = csubf(t0, t1);
    Z[3] = csubf(t2, t3);
}

__device__ __forceinline__ void build_tw256(float2* tw, int t)
{
    float sn, cs;
    sincosf(-2.0f * (float)M_PI * (float)t * (1.0f / 1024.0f), &sn, &cs);
    tw[t] = make_float2(cs, sn);
}

// ============================================================================
// bind + accumulate with deferred Hermitian extraction:
//   per row: S[f] += Z[f]^2 ; end: acc = (S[f] - conj(S[fn]))/(4i)
// ============================================================================
__global__ void __launch_bounds__(256) bind_accum_kernel()
{
    __shared__ float2 tw[256];
    __shared__ float2 bufA[1024];
    __shared__ float2 bufB[1024];

    const int t = threadIdx.x;
    const int c = blockIdx.x;
    const int b = blockIdx.y;
    build_tw256(tw, t);

    float2 S[4];
#pragma unroll
    for (int h = 0; h < 4; h++) S[h] = make_float2(0.f, 0.f);

    const size_t base = ((size_t)b * SEQ + (size_t)c * CROWS) * DIM;
    for (int r = 0; r < CROWS; r++) {
        const float* kp = g_k + base + (size_t)r * DIM;
        const float* vp = g_v + base + (size_t)r * DIM;
        fft_stage1_store(
            make_float2(kp[t],       vp[t]),
            make_float2(kp[t + 256], vp[t + 256]),
            make_float2(kp[t + 512], vp[t + 512]),
            make_float2(kp[t + 768], vp[t + 768]),
            bufA, tw, t, 0);
        fft_mid3(bufA, bufB, tw, t, 0);          // output in bufB
        float2 Z[4];
        fft_last_reg(bufB, t, 0, Z);
#pragma unroll
        for (int h = 0; h < 4; h++) {            // S += Z^2
            S[h].x += fmaf(Z[h].x, Z[h].x, -Z[h].y * Z[h].y);
            S[h].y += 2.0f * Z[h].x * Z[h].y;
        }
    }

#pragma unroll
    for (int h = 0; h < 4; h++) bufA[t + (h << 8)] = S[h];
    __syncthreads();
    float2* outp = g_part + ((size_t)b * NCH + c) * DIM;
#pragma unroll
    for (int h = 0; h < 4; h++) {
        const int f  = t + (h << 8);
        const int fn = (1024 - f) & 1023;
        const float2 Sn = bufA[fn];
        const float wr = S[h].x - Sn.x;
        const float wi = S[h].y + Sn.y;
        outp[f] = make_float2(0.25f * wi, -0.25f * wr);
    }
}

// ============================================================================
// reduce_Fs: 4 threads per frequency, each sums 64 chunks (coalesced),
// fixed-order 4-way combine in smem (deterministic).
// grid = (DIM/64, BATCH) = (16, 4), 256 threads.
// ============================================================================
__global__ void __launch_bounds__(256) reduce_Fs_kernel()
{
    __shared__ float2 part[256];
    const int b = blockIdx.y;
    const int t = threadIdx.x;
    const int f = blockIdx.x * 64 + (t & 63);
    const int i = t >> 6;                     // 0..3
    float2 s = make_float2(0.f, 0.f);
    const float2* p = g_part + (size_t)b * NCH * DIM + f;
#pragma unroll 8
    for (int c = i; c < NCH; c += 4) {
        const float2 v = p[(size_t)c * DIM];
        s.x += v.x; s.y += v.y;
    }
    part[t] = s;
    __syncthreads();
    if (i == 0) {
        const float2 s0 = part[t];
        const float2 s1 = part[t + 64];
        const float2 s2 = part[t + 128];
        const float2 s3 = part[t + 192];
        float2 r;
        r.x = (s0.x + s1.x) + (s2.x + s3.x);
        r.y = (s0.y + s1.y) + (s2.y + s3.y);
        g_Fs[b * DIM + f] = r;
    }
}

// ============================================================================
// output: two rows per block, combined Hermitian inverse FFT
// ============================================================================
__device__ __forceinline__ void compute_H_reg(
    const float2* Zreg, const float2* Zsm, const float2* Fsb, int t, float2* Hreg)
{
#pragma unroll
    for (int h = 0; h < 4; h++) {
        const int f  = t + (h << 8);
        const int fn = (1024 - f) & 1023;
        const float2 z1 = Zreg[h];
        const float2 z2 = Zsm[fn];
        const float2 Fq = make_float2(0.5f * (z1.x + z2.x), 0.5f * (z1.y - z2.y));
        const float dx = z1.x - z2.x, dy = z1.y + z2.y;
        const float2 Fr = make_float2(0.5f * dy, -0.5f * dx);
        const float mag2 = fmaf(Fr.x, Fr.x, Fr.y * Fr.y);
        const float2 G = make_float2(Fq.x - mag2, -Fq.y);
        Hreg[h] = cmulf(G, Fsb[f]);
    }
}

__global__ void __launch_bounds__(256) output_kernel(
    const float* __restrict__ x, float* __restrict__ out)
{
    __shared__ float2 tw[256];
    __shared__ float2 bufA[1024];
    __shared__ float2 bufB[1024];

    const int t = threadIdx.x;
    const int rowA = blockIdx.x * 2;
    const int rowB = rowA + 1;
    const int b = rowA >> 12;
    build_tw256(tw, t);

    const float2* Fsb = g_Fs + (size_t)b * DIM;
    const size_t baseA = (size_t)rowA * DIM;
    const size_t baseB = (size_t)rowB * DIM;

    // ---- row A forward ----
    {
        const float* qp = g_q + baseA;
        const float* rp = g_r + baseA;
        fft_stage1_store(
            make_float2(qp[t],       rp[t]),
            make_float2(qp[t + 256], rp[t + 256]),
            make_float2(qp[t + 512], rp[t + 512]),
            make_float2(qp[t + 768], rp[t + 768]),
            bufA, tw, t, 0);
    }
    fft_mid3(bufA, bufB, tw, t, 0);
    float2 ZA[4];
    fft_last_reg(bufB, t, 0, ZA);
#pragma unroll
    for (int h = 0; h < 4; h++) bufA[t + (h << 8)] = ZA[h];
    __syncthreads();
    float2 HA[4];
    compute_H_reg(ZA, bufA, Fsb, t, HA);

    // ---- row B forward ----
    {
        const float* qp = g_q + baseB;
        const float* rp = g_r + baseB;
        fft_stage1_store(
            make_float2(qp[t],       rp[t]),
            make_float2(qp[t + 256], rp[t + 256]),
            make_float2(qp[t + 512], rp[t + 512]),
            make_float2(qp[t + 768], rp[t + 768]),
            bufB, tw, t, 0);
    }
    fft_mid3(bufB, bufA, tw, t, 0);
    float2 ZB[4];
    fft_last_reg(bufA, t, 0, ZB);
#pragma unroll
    for (int h = 0; h < 4; h++) bufB[t + (h << 8)] = ZB[h];
    __syncthreads();
    float2 HB[4];
    compute_H_reg(ZB, bufB, Fsb, t, HB);

    // ---- combined inverse: ifft(HA + i*HB) ----
    float2 Hc[4];
#pragma unroll
    for (int h = 0; h < 4; h++)
        Hc[h] = make_float2(HA[h].x - HB[h].y, HA[h].y + HB[h].x);
    fft_stage1_store(Hc[0], Hc[1], Hc[2], Hc[3], bufA, tw, t, 1);
    fft_mid3(bufA, bufB, tw, t, 1);
    float2 R[4];
    fft_last_reg(bufB, t, 1, R);

    const float* xA = x + baseA;
    const float* xB = x + baseB;
    float* oA = out + baseA;
    float* oB = out + baseB;
#pragma unroll
    for (int h = 0; h < 4; h++) {
        const int i = t + (h << 8);
        oA[i] = xA[i] + R[h].x * (1.0f / 1024.0f);
        oB[i] = xB[i] + R[h].y * (1.0f / 1024.0f);
    }
}

// ============================================================================
// Launch
// ============================================================================
extern "C" void kernel_launch(void* const* d_in, const int* in_sizes, int n_in,
                              void* d_out, int out_size)
{
    const float* x  = (const float*)d_in[0];
    const float* Wq = (const float*)d_in[1];
    const float* bq = (const float*)d_in[2];
    const float* Wk = (const float*)d_in[3];
    const float* bk = (const float*)d_in[4];
    const float* Wv = (const float*)d_in[5];
    const float* bv = (const float*)d_in[6];
    const float* Wr = (const float*)d_in[7];
    const float* br = (const float*)d_in[8];
    float* out = (float*)d_out;

    static bool attr_set = false;
    if (!attr_set) {
        cudaFuncSetAttribute(gemm_mma_kernel,
                             cudaFuncAttributeMaxDynamicSharedMemorySize, SMEM_DYN);
        attr_set = true;
    }

    convert_all_kernel<<<16384 + 4096, 256>>>(x, Wq, Wk, Wv, Wr);

    gemm_mma_kernel<<<dim3(DIM / BN, MROWS / BM, 4), 256, SMEM_DYN>>>(bq, bk, bv, br);

    bind_accum_kernel<<<dim3(NCH, BATCH), 256>>>();
    reduce_Fs_kernel<<<dim3(DIM / 64, BATCH), 256>>>();
    output_kernel<<<MROWS / 2, 256>>>(x, out);
}

// round 17
// speedup vs baseline: 1.0979x; 1.0318x over previous
#include <cuda_runtime.h>
#include <cuda_fp16.h>
#include <math.h>
#include <stdint.h>

#define BATCH 4
#define SEQ   4096
#define DIM   1024
#define MROWS (BATCH*SEQ)       // 16384
#define NCH   256
#define CROWS (SEQ / NCH)       // 16

// ---- mma.sync GEMM tiling (single-term fp16, 2 CTAs/SM) ----
#define BM 128
#define BN 128
#define NB_CH 16                // K chunks (1024 / 64)
#define STAGES 3
#define A_ST (BM * 128)         // 16384 B
#define B_ST (BN * 128)         // 16384 B
#define STAGE_B (A_ST + B_ST)   // 32768
#define SMEM_DYN (STAGES * STAGE_B)   // 98304  (2 CTAs/SM)

// padded map for the m=4-write / m=16-read hop (2-way instead of 8-way)
#define PMAP(i) ((i) + ((i) >> 2))
#define FBUF 1280               // 1024 + 1024/4 padding

// -------- scratch (static device globals; no runtime allocation) -----------
__device__ __half g_xh[(size_t)MROWS * DIM];      // 32MB  hi only
__device__ __half g_we[4][(size_t)DIM * DIM];     // 8MB   hi only
__device__ float  g_q[(size_t)MROWS * DIM];
__device__ float  g_k[(size_t)MROWS * DIM];
__device__ float  g_v[(size_t)MROWS * DIM];
__device__ float  g_r[(size_t)MROWS * DIM];
__device__ float2 g_part[BATCH * NCH * DIM];
__device__ float2 g_Fs[BATCH * DIM];

// ============================================================================
// helpers
// ============================================================================
__device__ __forceinline__ uint32_t smem_u32(const void* p) {
    uint32_t a;
    asm("{ .reg .u64 t; cvta.to.shared.u64 t, %1; cvt.u32.u64 %0, t; }" : "=r"(a) : "l"(p));
    return a;
}

__device__ __forceinline__ void cp16(uint32_t dst, const void* src) {
    asm volatile("cp.async.cg.shared.global [%0], [%1], 16;" :: "r"(dst), "l"(src) : "memory");
}
#define CP_COMMIT() asm volatile("cp.async.commit_group;" ::: "memory")
#define CP_WAIT1()  asm volatile("cp.async.wait_group 1;" ::: "memory")

__device__ __forceinline__ void ldmx4(uint32_t& r0, uint32_t& r1, uint32_t& r2, uint32_t& r3,
                                      uint32_t addr) {
    asm volatile("ldmatrix.sync.aligned.m8n8.x4.shared.b16 {%0,%1,%2,%3}, [%4];"
                 : "=r"(r0), "=r"(r1), "=r"(r2), "=r"(r3) : "r"(addr));
}

__device__ __forceinline__ void mma16816(float* c, uint32_t a0, uint32_t a1, uint32_t a2,
                                         uint32_t a3, uint32_t b0, uint32_t b1) {
    asm volatile(
        "mma.sync.aligned.m16n8k16.row.col.f32.f16.f16.f32 "
        "{%0,%1,%2,%3}, {%4,%5,%6,%7}, {%8,%9}, {%0,%1,%2,%3};"
        : "+f"(c[0]), "+f"(c[1]), "+f"(c[2]), "+f"(c[3])
        : "r"(a0), "r"(a1), "r"(a2), "r"(a3), "r"(b0), "r"(b1));
}

__device__ __forceinline__ float tanh_fast(float x) {
    float ax = fabsf(x);
    float e = __expf(-2.0f * ax);
    float t = __fdividef(1.0f - e, 1.0f + e);
    return copysignf(t, x);
}

// swizzled smem byte offset within a (rows x 128B) tile
__device__ __forceinline__ uint32_t swz(uint32_t row, uint32_t cg) {
    return row * 128u + ((cg ^ (row & 7u)) << 4);
}

// ============================================================================
// Merged conversion: one launch covers x (blocks 0..16383) and W (16384..20479)
// ============================================================================
__global__ void __launch_bounds__(256) convert_all_kernel(
    const float* __restrict__ x,
    const float* __restrict__ Wq, const float* __restrict__ Wk,
    const float* __restrict__ Wv, const float* __restrict__ Wr)
{
    const int bid = blockIdx.x;
    if (bid < 16384) {
        const size_t base = ((size_t)bid * 256 + threadIdx.x) * 4;
        const float4 v = *(const float4*)(x + base);
        __half2 h0 = make_half2(__float2half(v.x), __float2half(v.y));
        __half2 h1 = make_half2(__float2half(v.z), __float2half(v.w));
        __half2* p = (__half2*)(g_xh + base);
        p[0] = h0; p[1] = h1;
    } else {
        const int wb = bid - 16384;
        const int w = wb >> 10;
        const float* W = (w == 0) ? Wq : (w == 1) ? Wk : (w == 2) ? Wv : Wr;
        const size_t base = ((size_t)(wb & 1023) * 256 + threadIdx.x) * 4;
        const float4 v = *(const float4*)(W + base);
        __half2 h0 = make_half2(__float2half(v.x), __float2half(v.y));
        __half2 h1 = make_half2(__float2half(v.z), __float2half(v.w));
        __half2* p = (__half2*)(g_we[w] + base);
        p[0] = h0; p[1] = h1;
    }
}

// ============================================================================
// fp16 mma.sync GEMM (single term): C = tanh(Ah@Bh^T + bias)
// BM=128 x BN=128, 8 warps (warp 64x32), 2 CTAs/SM. grid.z selects weight.
// (round-13 configuration — best measured)
// ============================================================================
__global__ void __launch_bounds__(256, 2) gemm_mma_kernel(
    const float* __restrict__ bq, const float* __restrict__ bk,
    const float* __restrict__ bv, const float* __restrict__ br)
{
    extern __shared__ char dsm[];
    const uint32_t smem = smem_u32(dsm);

    const int tid = threadIdx.x, wid = tid >> 5, lane = tid & 31;
    const int nb = blockIdx.x, mb = blockIdx.y, sel = blockIdx.z;
    const int wm = wid & 1, wn = wid >> 1;       // warp tile 64(m) x 32(n)
    const float* bias_g = (sel == 0) ? bq : (sel == 1) ? bk : (sel == 2) ? bv : br;
    float* C = (sel == 0) ? g_q : (sel == 1) ? g_k : (sel == 2) ? g_v : g_r;

    const char* a_base = (const char*)g_xh + (size_t)mb * BM * 2048;      // 2048B/row
    const char* b_base = (const char*)g_we[sel] + (size_t)nb * BN * 2048; // 2048B/row

    const uint32_t crow0 = (uint32_t)(tid >> 3);   // 0..31
    const uint32_t ccg = (uint32_t)(tid & 7);

    float acc[4][4][4];
#pragma unroll
    for (int i = 0; i < 4; i++)
#pragma unroll
        for (int j = 0; j < 4; j++)
#pragma unroll
            for (int q = 0; q < 4; q++) acc[i][j][q] = 0.f;

    auto issue = [&](int stage, int bc) {
        const uint32_t sA = smem + stage * STAGE_B;
        const uint32_t sB = sA + A_ST;
#pragma unroll
        for (int j = 0; j < 4; j++) {
            const uint32_t r = crow0 + 32u * j;          // 0..127
            cp16(sA + swz(r, ccg), a_base + (size_t)r * 2048 + bc * 128 + ccg * 16);
        }
#pragma unroll
        for (int j = 0; j < 4; j++) {
            const uint32_t r = crow0 + 32u * j;
            cp16(sB + swz(r, ccg), b_base + (size_t)r * 2048 + bc * 128 + ccg * 16);
        }
    };

    issue(0, 0); CP_COMMIT();
    issue(1, 1); CP_COMMIT();

    const uint32_t a_row = (uint32_t)(wm * 64 + (lane & 15));
    const uint32_t a_kg  = (uint32_t)(lane >> 4);
    const uint32_t b_row = (uint32_t)(wn * 32 + (lane & 7) + ((lane >> 4) << 3));
    const uint32_t b_kg  = (uint32_t)((lane >> 3) & 1);

    for (int bc = 0; bc < NB_CH; bc++) {
        const int s = bc % STAGES;
        CP_WAIT1();
        __syncthreads();
        if (bc + 2 < NB_CH) issue((bc + 2) % STAGES, bc + 2);
        CP_COMMIT();

        const uint32_t sA = smem + s * STAGE_B;
        const uint32_t sB = sA + A_ST;

#pragma unroll
        for (int ks = 0; ks < 4; ks++) {
            uint32_t a[4][4];
#pragma unroll
            for (int mf = 0; mf < 4; mf++)
                ldmx4(a[mf][0], a[mf][1], a[mf][2], a[mf][3],
                      sA + swz(a_row + mf * 16, a_kg + ks * 2));
            uint32_t b[2][4];
#pragma unroll
            for (int nf2 = 0; nf2 < 2; nf2++)
                ldmx4(b[nf2][0], b[nf2][1], b[nf2][2], b[nf2][3],
                      sB + swz(b_row + nf2 * 16, b_kg + ks * 2));
#pragma unroll
            for (int mf = 0; mf < 4; mf++) {
#pragma unroll
                for (int nf2 = 0; nf2 < 2; nf2++) {
                    mma16816(acc[mf][nf2 * 2 + 0], a[mf][0], a[mf][1], a[mf][2], a[mf][3],
                             b[nf2][0], b[nf2][1]);
                    mma16816(acc[mf][nf2 * 2 + 1], a[mf][0], a[mf][1], a[mf][2], a[mf][3],
                             b[nf2][2], b[nf2][3]);
                }
            }
        }
    }

    // epilogue: bias + tanh + fp32 store
#pragma unroll
    for (int mf = 0; mf < 4; mf++) {
        const int r0 = mb * BM + wm * 64 + mf * 16 + (lane >> 2);
        const int r1 = r0 + 8;
#pragma unroll
        for (int nf = 0; nf < 4; nf++) {
            const int col = nb * BN + wn * 32 + nf * 8 + (lane & 3) * 2;
            const float2 b2 = *(const float2*)(bias_g + col);
            float2 o0, o1;
            o0.x = tanh_fast(acc[mf][nf][0] + b2.x);
            o0.y = tanh_fast(acc[mf][nf][1] + b2.y);
            o1.x = tanh_fast(acc[mf][nf][2] + b2.x);
            o1.y = tanh_fast(acc[mf][nf][3] + b2.y);
            *(float2*)(C + (size_t)r0 * DIM + col) = o0;
            *(float2*)(C + (size_t)r1 * DIM + col) = o1;
        }
    }
}

// ============================================================================
// Radix-4 Stockham FFT, N=1024, 256 threads, 5 stages:
//   stage m=1   : fused with data source -> smem (plain, conflict-free)
//   stage m=4   : read plain, write P-MAPPED (2-way instead of 8-way)
//   stage m=16  : read P-mapped, write plain (2-way floor)
//   stage m=64  : plain (conflict-free)
//   stage m=256 : jm=0, twiddles=1 -> fused into registers
// ============================================================================
__device__ __forceinline__ float2 cmulf(float2 a, float2 b) {
    return make_float2(fmaf(a.x, b.x, -a.y * b.y), fmaf(a.x, b.y, a.y * b.x));
}
__device__ __forceinline__ float2 caddf(float2 a, float2 b) {
    return make_float2(a.x + b.x, a.y + b.y);
}
__device__ __forceinline__ float2 csubf(float2 a, float2 b) {
    return make_float2(a.x - b.x, a.y - b.y);
}

__device__ __forceinline__ void fft_stage1_store(
    float2 x0, float2 x1, float2 x2, float2 x3,
    float2* dst, const float2* tw, int t, int inv)
{
    const float2 t0 = caddf(x0, x2);
    const float2 t1 = caddf(x1, x3);
    const float2 t2 = csubf(x0, x2);
    const float2 d  = csubf(x1, x3);
    const float2 t3 = inv ? make_float2(-d.y, d.x) : make_float2(d.y, -d.x);
    float2 w1 = tw[t];
    if (inv) w1.y = -w1.y;
    const float2 w2 = cmulf(w1, w1);
    const float2 w3 = cmulf(w2, w1);
    const float2 y0 = caddf(t0, t1);
    const float2 y1 = cmulf(w1, caddf(t2, t3));
    const float2 y2 = cmulf(w2, csubf(t0, t1));
    const float2 y3 = cmulf(w3, csubf(t2, t3));
    float4* d4 = (float4*)(dst + 4 * t);
    d4[0] = make_float4(y0.x, y0.y, y1.x, y1.y);
    d4[1] = make_float4(y2.x, y2.y, y3.x, y3.y);
}

// one radix-4 butterfly given 4 inputs; writes via caller-provided indices
#define R4_BODY(X0, X1, X2, X3, JM)                                          \
    const float2 t0 = caddf(X0, X2);                                         \
    const float2 t1 = caddf(X1, X3);                                         \
    const float2 t2 = csubf(X0, X2);                                         \
    const float2 d  = csubf(X1, X3);                                         \
    const float2 t3 = inv ? make_float2(-d.y, d.x) : make_float2(d.y, -d.x); \
    float2 w1 = tw[JM];                                                      \
    if (inv) w1.y = -w1.y;                                                   \
    const float2 w2 = cmulf(w1, w1);                                         \
    const float2 w3 = cmulf(w2, w1);                                         \
    const float2 y0 = caddf(t0, t1);                                         \
    const float2 y1 = cmulf(w1, caddf(t2, t3));                              \
    const float2 y2 = cmulf(w2, csubf(t0, t1));                              \
    const float2 y3 = cmulf(w3, csubf(t2, t3));

// middle 3 stages with targeted conflict-avoiding layout on the a->b hop.
// a: plain buffer in, b: P-mapped intermediate. Final output (m=64) in b, plain.
__device__ __forceinline__ void fft_mid3(
    float2* a, float2* b, const float2* tw, int t, int inv)
{
    {   // m = 4 : read a plain, write b P-mapped
        __syncthreads();
        const int k = t & 3, jm = t - k;
        const float2 x0 = a[t], x1 = a[t + 256], x2 = a[t + 512], x3 = a[t + 768];
        R4_BODY(x0, x1, x2, x3, jm)
        const int o = 4 * jm + k;
        b[PMAP(o)]      = y0;
        b[PMAP(o + 4)]  = y1;
        b[PMAP(o + 8)]  = y2;
        b[PMAP(o + 12)] = y3;
    }
    {   // m = 16 : read b P-mapped, write a plain
        __syncthreads();
        const int k = t & 15, jm = t - k;
        const float2 x0 = b[PMAP(t)],       x1 = b[PMAP(t + 256)];
        const float2 x2 = b[PMAP(t + 512)], x3 = b[PMAP(t + 768)];
        R4_BODY(x0, x1, x2, x3, jm)
        const int o = 4 * jm + k;
        a[o]      = y0;
        a[o + 16] = y1;
        a[o + 32] = y2;
        a[o + 48] = y3;
    }
    {   // m = 64 : plain both sides (conflict-free)
        __syncthreads();
        const int k = t & 63, jm = t - k;
        const float2 x0 = a[t], x1 = a[t + 256], x2 = a[t + 512], x3 = a[t + 768];
        R4_BODY(x0, x1, x2, x3, jm)
        const int o = 4 * jm + k;
        b[o]       = y0;
        b[o + 64]  = y1;
        b[o + 128] = y2;
        b[o + 192] = y3;
    }
}

__device__ __forceinline__ void fft_last_reg(
    const float2* src, int t, int inv, float2* Z)
{
    __syncthreads();
    const float2 x0 = src[t];
    const float2 x1 = src[t + 256];
    const float2 x2 = src[t + 512];
    const float2 x3 = src[t + 768];
    const float2 t0 = caddf(x0, x2);
    const float2 t1 = caddf(x1, x3);
    const float2 t2 = csubf(x0, x2);
    const float2 d  = csubf(x1, x3);
    const float2 t3 = inv ? make_float2(-d.y, d.x) : make_float2(d.y, -d.x);
    Z[0] = caddf(t0, t1);
    Z[1] = caddf(t2, t3);
    Z[2] = csubf(t0, t1);
    Z[3] = csubf(t2, t3);
}

__device__ __forceinline__ void build_tw256(float2* tw, int t)
{
    float sn, cs;
    sincosf(-2.0f * (float)M_PI * (float)t * (1.0f / 1024.0f), &sn, &cs);
    tw[t] = make_float2(cs, sn);
}

// ============================================================================
// bind + accumulate with deferred Hermitian extraction
// ============================================================================
__global__ void __launch_bounds__(256) bind_accum_kernel()
{
    __shared__ float2 tw[256];
    __shared__ float2 bufA[FBUF];
    __shared__ float2 bufB[FBUF];

    const int t = threadIdx.x;
    const int c = blockIdx.x;
    const int b = blockIdx.y;
    build_tw256(tw, t);

    float2 S[4];
#pragma unroll
    for (int h = 0; h < 4; h++) S[h] = make_float2(0.f, 0.f);

    const size_t base = ((size_t)b * SEQ + (size_t)c * CROWS) * DIM;
    for (int r = 0; r < CROWS; r++) {
        const float* kp = g_k + base + (size_t)r * DIM;
        const float* vp = g_v + base + (size_t)r * DIM;
        fft_stage1_store(
            make_float2(kp[t],       vp[t]),
            make_float2(kp[t + 256], vp[t + 256]),
            make_float2(kp[t + 512], vp[t + 512]),
            make_float2(kp[t + 768], vp[t + 768]),
            bufA, tw, t, 0);
        fft_mid3(bufA, bufB, tw, t, 0);          // output in bufB (plain)
        float2 Z[4];
        fft_last_reg(bufB, t, 0, Z);
#pragma unroll
        for (int h = 0; h < 4; h++) {            // S += Z^2
            S[h].x += fmaf(Z[h].x, Z[h].x, -Z[h].y * Z[h].y);
            S[h].y += 2.0f * Z[h].x * Z[h].y;
        }
    }

#pragma unroll
    for (int h = 0; h < 4; h++) bufA[t + (h << 8)] = S[h];
    __syncthreads();
    float2* outp = g_part + ((size_t)b * NCH + c) * DIM;
#pragma unroll
    for (int h = 0; h < 4; h++) {
        const int f  = t + (h << 8);
        const int fn = (1024 - f) & 1023;
        const float2 Sn = bufA[fn];
        const float wr = S[h].x - Sn.x;
        const float wi = S[h].y + Sn.y;
        outp[f] = make_float2(0.25f * wi, -0.25f * wr);
    }
}

// ============================================================================
// reduce_Fs: 4 threads per frequency, fixed-order combine (deterministic)
// ============================================================================
__global__ void __launch_bounds__(256) reduce_Fs_kernel()
{
    __shared__ float2 part[256];
    const int b = blockIdx.y;
    const int t = threadIdx.x;
    const int f = blockIdx.x * 64 + (t & 63);
    const int i = t >> 6;                     // 0..3
    float2 s = make_float2(0.f, 0.f);
    const float2* p = g_part + (size_t)b * NCH * DIM + f;
#pragma unroll 8
    for (int c = i; c < NCH; c += 4) {
        const float2 v = p[(size_t)c * DIM];
        s.x += v.x; s.y += v.y;
    }
    part[t] = s;
    __syncthreads();
    if (i == 0) {
        const float2 s0 = part[t];
        const float2 s1 = part[t + 64];
        const float2 s2 = part[t + 128];
        const float2 s3 = part[t + 192];
        float2 r;
        r.x = (s0.x + s1.x) + (s2.x + s3.x);
        r.y = (s0.y + s1.y) + (s2.y + s3.y);
        g_Fs[b * DIM + f] = r;
    }
}

// ============================================================================
// output: two rows per block, combined Hermitian inverse FFT
// ============================================================================
__device__ __forceinline__ void compute_H_reg(
    const float2* Zreg, const float2* Zsm, const float2* Fsb, int t, float2* Hreg)
{
#pragma unroll
    for (int h = 0; h < 4; h++) {
        const int f  = t + (h << 8);
        const int fn = (1024 - f) & 1023;
        const float2 z1 = Zreg[h];
        const float2 z2 = Zsm[fn];
        const float2 Fq = make_float2(0.5f * (z1.x + z2.x), 0.5f * (z1.y - z2.y));
        const float dx = z1.x - z2.x, dy = z1.y + z2.y;
        const float2 Fr = make_float2(0.5f * dy, -0.5f * dx);
        const float mag2 = fmaf(Fr.x, Fr.x, Fr.y * Fr.y);
        const float2 G = make_float2(Fq.x - mag2, -Fq.y);
        Hreg[h] = cmulf(G, Fsb[f]);
    }
}

__global__ void __launch_bounds__(256) output_kernel(
    const float* __restrict__ x, float* __restrict__ out)
{
    __shared__ float2 tw[256];
    __shared__ float2 bufA[FBUF];
    __shared__ float2 bufB[FBUF];

    const int t = threadIdx.x;
    const int rowA = blockIdx.x * 2;
    const int rowB = rowA + 1;
    const int b = rowA >> 12;
    build_tw256(tw, t);

    const float2* Fsb = g_Fs + (size_t)b * DIM;
    const size_t baseA = (size_t)rowA * DIM;
    const size_t baseB = (size_t)rowB * DIM;

    // ---- row A forward ----
    {
        const float* qp = g_q + baseA;
        const float* rp = g_r + baseA;
        fft_stage1_store(
            make_float2(qp[t],       rp[t]),
            make_float2(qp[t + 256], rp[t + 256]),
            make_float2(qp[t + 512], rp[t + 512]),
            make_float2(qp[t + 768], rp[t + 768]),
            bufA, tw, t, 0);
    }
    fft_mid3(bufA, bufB, tw, t, 0);    // result in bufB (plain)
    float2 ZA[4];
    fft_last_reg(bufB, t, 0, ZA);
#pragma unroll
    for (int h = 0; h < 4; h++) bufA[t + (h << 8)] = ZA[h];
    __syncthreads();
    float2 HA[4];
    compute_H_reg(ZA, bufA, Fsb, t, HA);

    // ---- row B forward (buffers swapped; both are FBUF-sized) ----
    {
        const float* qp = g_q + baseB;
        const float* rp = g_r + baseB;
        fft_stage1_store(
            make_float2(qp[t],       rp[t]),
            make_float2(qp[t + 256], rp[t + 256]),
            make_float2(qp[t + 512], rp[t + 512]),
            make_float2(qp[t + 768], rp[t + 768]),
            bufB, tw, t, 0);
    }
    fft_mid3(bufB, bufA, tw, t, 0);    // result in bufA (plain)
    float2 ZB[4];
    fft_last_reg(bufA, t, 0, ZB);
#pragma unroll
    for (int h = 0; h < 4; h++) bufB[t + (h << 8)] = ZB[h];
    __syncthreads();
    float2 HB[4];
    compute_H_reg(ZB, bufB, Fsb, t, HB);

    // ---- combined inverse: ifft(HA + i*HB) ----
    float2 Hc[4];
#pragma unroll
    for (int h = 0; h < 4; h++)
        Hc[h] = make_float2(HA[h].x - HB[h].y, HA[h].y + HB[h].x);
    fft_stage1_store(Hc[0], Hc[1], Hc[2], Hc[3], bufA, tw, t, 1);
    fft_mid3(bufA, bufB, tw, t, 1);    // result in bufB (plain)
    float2 R[4];
    fft_last_reg(bufB, t, 1, R);

    const float* xA = x + baseA;
    const float* xB = x + baseB;
    float* oA = out + baseA;
    float* oB = out + baseB;
#pragma unroll
    for (int h = 0; h < 4; h++) {
        const int i = t + (h << 8);
        oA[i] = xA[i] + R[h].x * (1.0f / 1024.0f);
        oB[i] = xB[i] + R[h].y * (1.0f / 1024.0f);
    }
}

// ============================================================================
// Launch
// ============================================================================
extern "C" void kernel_launch(void* const* d_in, const int* in_sizes, int n_in,
                              void* d_out, int out_size)
{
    const float* x  = (const float*)d_in[0];
    const float* Wq = (const float*)d_in[1];
    const float* bq = (const float*)d_in[2];
    const float* Wk = (const float*)d_in[3];
    const float* bk = (const float*)d_in[4];
    const float* Wv = (const float*)d_in[5];
    const float* bv = (const float*)d_in[6];
    const float* Wr = (const float*)d_in[7];
    const float* br = (const float*)d_in[8];
    float* out = (float*)d_out;

    static bool attr_set = false;
    if (!attr_set) {
        cudaFuncSetAttribute(gemm_mma_kernel,
                             cudaFuncAttributeMaxDynamicSharedMemorySize, SMEM_DYN);
        attr_set = true;
    }

    convert_all_kernel<<<16384 + 4096, 256>>>(x, Wq, Wk, Wv, Wr);

    gemm_mma_kernel<<<dim3(DIM / BN, MROWS / BM, 4), 256, SMEM_DYN>>>(bq, bk, bv, br);

    bind_accum_kernel<<<dim3(NCH, BATCH), 256>>>();
    reduce_Fs_kernel<<<dim3(DIM / 64, BATCH), 256>>>();
    output_kernel<<<MROWS / 2, 256>>>(x, out);
}